// round 3
// baseline (speedup 1.0000x reference)
#include <cuda_runtime.h>
#include <cuda_bf16.h>
#include <cstdint>

#define N_NODES 100000
#define N_EDGES 600000
#define HID 128
#define OUT 24

// ---------------- scratch ----------------
__device__ float g_h  [(size_t)N_NODES * HID];
__device__ float g_agg[(size_t)N_NODES * HID];
__device__ float g_hid[(size_t)N_NODES * HID];

// ---------------- packed f32x2 helpers ----------------
__device__ __forceinline__ unsigned long long pk2(float lo, float hi) {
    unsigned long long r;
    asm("mov.b64 %0, {%1, %2};" : "=l"(r) : "f"(lo), "f"(hi));
    return r;
}
__device__ __forceinline__ void fma2(unsigned long long& d,
                                     unsigned long long a, unsigned long long b) {
    asm("fma.rn.f32x2 %0, %1, %2, %0;" : "+l"(d) : "l"(a), "l"(b));
}
__device__ __forceinline__ float2 upk(unsigned long long v) {
    float2 f;
    asm("mov.b64 {%0, %1}, %2;" : "=f"(f.x), "=f"(f.y) : "l"(v));
    return f;
}
__device__ __forceinline__ void red_add_v4(float* addr, float4 v) {
    asm volatile("red.global.add.v4.f32 [%0], {%1, %2, %3, %4};"
                 :: "l"(addr), "f"(v.x), "f"(v.y), "f"(v.z), "f"(v.w)
                 : "memory");
}

// ---------------- SGEMM: C[M,128]=(A(+A2))[M,K]@W[K,128](+bias)(+relu) ----
#define BM 128
#define BN 128
#define BK 16

template<bool RELU>
__global__ __launch_bounds__(256)
void sgemm_kernel(const float* __restrict__ A,
                  const float* __restrict__ A2,   // optional elementwise add
                  int lda,
                  const float* __restrict__ W, int ldw,
                  const float* __restrict__ bias,
                  float* __restrict__ C, int ldc,
                  int M, int K)
{
    __shared__ float As[BK][BM];
    __shared__ float Ws[BK][BN];

    const int tid = threadIdx.x;
    const int m0 = blockIdx.y * BM;
    const int tx = tid & 15;
    const int ty = tid >> 4;

    unsigned long long acc2[8][4];
    #pragma unroll
    for (int i = 0; i < 8; i++)
        #pragma unroll
        for (int j = 0; j < 4; j++) acc2[i][j] = 0ull;

    for (int k0 = 0; k0 < K; k0 += BK) {
        #pragma unroll
        for (int p = 0; p < 2; p++) {
            int idx = tid + p * 256;
            int m   = idx >> 2;
            int k4  = (idx & 3) << 2;
            float4 v = make_float4(0.f, 0.f, 0.f, 0.f);
            int gm = m0 + m;
            if (gm < M) {
                v = *reinterpret_cast<const float4*>(A + (size_t)gm * lda + k0 + k4);
                if (A2) {
                    float4 w = *reinterpret_cast<const float4*>(A2 + (size_t)gm * lda + k0 + k4);
                    v.x += w.x; v.y += w.y; v.z += w.z; v.w += w.w;
                }
            }
            As[k4 + 0][m] = v.x;
            As[k4 + 1][m] = v.y;
            As[k4 + 2][m] = v.z;
            As[k4 + 3][m] = v.w;
        }
        #pragma unroll
        for (int p = 0; p < 2; p++) {
            int idx = tid + p * 256;
            int k   = idx >> 5;
            int n4  = (idx & 31) << 2;
            *reinterpret_cast<float4*>(&Ws[k][n4]) =
                *reinterpret_cast<const float4*>(W + (size_t)(k0 + k) * ldw + n4);
        }
        __syncthreads();

        #pragma unroll
        for (int kk = 0; kk < BK; kk++) {
            float a[8];
            *reinterpret_cast<float4*>(&a[0]) = *reinterpret_cast<float4*>(&As[kk][ty * 8]);
            *reinterpret_cast<float4*>(&a[4]) = *reinterpret_cast<float4*>(&As[kk][ty * 8 + 4]);
            unsigned long long b2[4];
            const unsigned long long* bp =
                reinterpret_cast<const unsigned long long*>(&Ws[kk][tx * 8]);
            #pragma unroll
            for (int j = 0; j < 4; j++) b2[j] = bp[j];
            #pragma unroll
            for (int i = 0; i < 8; i++) {
                unsigned long long a2 = pk2(a[i], a[i]);
                #pragma unroll
                for (int j = 0; j < 4; j++)
                    fma2(acc2[i][j], a2, b2[j]);
            }
        }
        __syncthreads();
    }

    const int gn = tx * 8;
    float4 bia0 = make_float4(0.f,0.f,0.f,0.f), bia1 = bia0;
    if (bias) {
        bia0 = *reinterpret_cast<const float4*>(bias + gn);
        bia1 = *reinterpret_cast<const float4*>(bias + gn + 4);
    }
    #pragma unroll
    for (int i = 0; i < 8; i++) {
        int gm = m0 + ty * 8 + i;
        if (gm >= M) continue;
        float2 p0 = upk(acc2[i][0]), p1 = upk(acc2[i][1]);
        float2 p2 = upk(acc2[i][2]), p3 = upk(acc2[i][3]);
        float4 v0 = make_float4(p0.x + bia0.x, p0.y + bia0.y, p1.x + bia0.z, p1.y + bia0.w);
        float4 v1 = make_float4(p2.x + bia1.x, p2.y + bia1.y, p3.x + bia1.z, p3.y + bia1.w);
        if (RELU) {
            v0.x = fmaxf(v0.x, 0.f); v0.y = fmaxf(v0.y, 0.f);
            v0.z = fmaxf(v0.z, 0.f); v0.w = fmaxf(v0.w, 0.f);
            v1.x = fmaxf(v1.x, 0.f); v1.y = fmaxf(v1.y, 0.f);
            v1.z = fmaxf(v1.z, 0.f); v1.w = fmaxf(v1.w, 0.f);
        }
        float* cp = C + (size_t)gm * ldc + gn;
        *reinterpret_cast<float4*>(cp)     = v0;
        *reinterpret_cast<float4*>(cp + 4) = v1;
    }
}

// ---------------- zero kernel ----------------
__global__ void zero_kernel(float4* __restrict__ dst, int n4)
{
    int i = blockIdx.x * blockDim.x + threadIdx.x;
    if (i < n4) dst[i] = make_float4(0.f, 0.f, 0.f, 0.f);
}

// ---------------- fused edge-embedding + message + v4-scatter --------------
// 128 threads, 32 edges/block.
// Phase 1: m_s[e][d] = relu(h[src][d] + ea@ew + eb)  (thread d, reg-held ew col)
// Phase 2: red.global.add.v4 of m_s into agg[dst]
__global__ __launch_bounds__(128)
void edge_scatter_kernel(const float* __restrict__ h,
                         const int* __restrict__ src,
                         const int* __restrict__ dst,
                         const float* __restrict__ ea,
                         const float* __restrict__ ew,
                         const float* __restrict__ eb,
                         float* __restrict__ agg,
                         int E)
{
    __shared__ float m_s[32][HID];
    __shared__ float ea_s[32][32];
    __shared__ int src_s[32];
    __shared__ int dst_s[32];

    const int d = threadIdx.x;
    unsigned long long wcol2[16];
    #pragma unroll
    for (int t = 0; t < 16; t++)
        wcol2[t] = pk2(ew[(2 * t) * HID + d], ew[(2 * t + 1) * HID + d]);
    const float bd = eb[d];

    const int base = blockIdx.x * 32;
    const int ne = min(32, E - base);
    if (ne <= 0) return;

    for (int idx = threadIdx.x; idx < ne * 32; idx += 128)
        ea_s[idx >> 5][idx & 31] = ea[(size_t)base * 32 + idx];
    if (threadIdx.x < ne) {
        src_s[threadIdx.x] = src[base + threadIdx.x];
        dst_s[threadIdx.x] = dst[base + threadIdx.x];
    }
    __syncthreads();

    float hs = h[(size_t)src_s[0] * HID + d];
    for (int e = 0; e < ne; e++) {
        float hs_next = 0.f;
        if (e + 1 < ne) hs_next = h[(size_t)src_s[e + 1] * HID + d];
        const unsigned long long* eav =
            reinterpret_cast<const unsigned long long*>(&ea_s[e][0]);
        unsigned long long ac0 = 0ull, ac1 = 0ull;
        #pragma unroll
        for (int t = 0; t < 8; t++) {
            fma2(ac0, eav[2 * t],     wcol2[2 * t]);
            fma2(ac1, eav[2 * t + 1], wcol2[2 * t + 1]);
        }
        float2 s0 = upk(ac0), s1 = upk(ac1);
        m_s[e][d] = fmaxf((s0.x + s0.y) + (s1.x + s1.y) + bd + hs, 0.f);
        hs = hs_next;
    }
    __syncthreads();

    // phase 2: 32 quads per edge, v4 reductions
    for (int idx = threadIdx.x; idx < ne * 32; idx += 128) {
        int e = idx >> 5;
        int q = idx & 31;
        float4 v = *reinterpret_cast<float4*>(&m_s[e][q * 4]);
        red_add_v4(&agg[(size_t)dst_s[e] * HID + q * 4], v);
    }
}

// ---------------- fused classifier: hidden + @cls_w2 -----------------------
#define CLS_E 64
#define HPAD 132

__global__ __launch_bounds__(128)
void cls_fused_kernel(const float* __restrict__ P,
                      const float* __restrict__ Q,
                      const int* __restrict__ src,
                      const int* __restrict__ dst,
                      const float* __restrict__ ea,
                      const float* __restrict__ w1c,  // [32,128]
                      const float* __restrict__ b1,   // [128]
                      const float* __restrict__ w2,   // [128,24]
                      const float* __restrict__ b2,   // [24]
                      float* __restrict__ out,        // [E,24]
                      int E)
{
    __shared__ float hid_s[CLS_E][HPAD];
    __shared__ float w2t[OUT][HPAD];
    __shared__ float ea_s[CLS_E][32];
    __shared__ int src_s[CLS_E];
    __shared__ int dst_s[CLS_E];

    const int tid = threadIdx.x;
    const int base = blockIdx.x * CLS_E;
    const int ne = min(CLS_E, E - base);
    if (ne <= 0) return;

    for (int idx = tid; idx < HID * OUT; idx += 128) {
        float v = w2[idx];
        w2t[idx % OUT][idx / OUT] = v;
    }
    for (int idx = tid; idx < ne * 32; idx += 128)
        ea_s[idx >> 5][idx & 31] = ea[(size_t)base * 32 + idx];
    if (tid < ne) {
        src_s[tid] = src[base + tid];
        dst_s[tid] = dst[base + tid];
    }
    __syncthreads();

    // ---- phase 1: hidden ----
    {
        const int d = tid;
        unsigned long long wcol2[16];
        #pragma unroll
        for (int t = 0; t < 16; t++)
            wcol2[t] = pk2(w1c[(2 * t) * HID + d], w1c[(2 * t + 1) * HID + d]);
        const float bd = b1[d];

        float pq = P[(size_t)src_s[0] * HID + d] + Q[(size_t)dst_s[0] * HID + d];
        for (int e = 0; e < ne; e++) {
            float pq_next = 0.f;
            if (e + 1 < ne)
                pq_next = P[(size_t)src_s[e + 1] * HID + d] +
                          Q[(size_t)dst_s[e + 1] * HID + d];
            const unsigned long long* eav =
                reinterpret_cast<const unsigned long long*>(&ea_s[e][0]);
            unsigned long long ac0 = 0ull, ac1 = 0ull;
            #pragma unroll
            for (int t = 0; t < 8; t++) {
                fma2(ac0, eav[2 * t],     wcol2[2 * t]);
                fma2(ac1, eav[2 * t + 1], wcol2[2 * t + 1]);
            }
            float2 s0 = upk(ac0), s1 = upk(ac1);
            hid_s[e][d] = fmaxf((s0.x + s0.y) + (s1.x + s1.y) + bd + pq, 0.f);
            pq = pq_next;
        }
    }
    __syncthreads();

    // ---- phase 2: [64 x 24] = hid_s[64 x 128] @ w2t^T ----
    const int oq = tid & 7;
    const int eq = tid >> 3;
    const int o0 = oq * 3;
    const int e0 = eq * 4;

    unsigned long long acc2[4][3];
    #pragma unroll
    for (int i = 0; i < 4; i++)
        #pragma unroll
        for (int j = 0; j < 3; j++) acc2[i][j] = 0ull;

    #pragma unroll 4
    for (int dch = 0; dch < HID; dch += 4) {
        unsigned long long h2[4][2], w2r[3][2];
        #pragma unroll
        for (int i = 0; i < 4; i++) {
            const unsigned long long* hp =
                reinterpret_cast<const unsigned long long*>(&hid_s[e0 + i][dch]);
            h2[i][0] = hp[0]; h2[i][1] = hp[1];
        }
        #pragma unroll
        for (int j = 0; j < 3; j++) {
            const unsigned long long* wp =
                reinterpret_cast<const unsigned long long*>(&w2t[o0 + j][dch]);
            w2r[j][0] = wp[0]; w2r[j][1] = wp[1];
        }
        #pragma unroll
        for (int i = 0; i < 4; i++)
            #pragma unroll
            for (int j = 0; j < 3; j++) {
                fma2(acc2[i][j], h2[i][0], w2r[j][0]);
                fma2(acc2[i][j], h2[i][1], w2r[j][1]);
            }
    }

    #pragma unroll
    for (int i = 0; i < 4; i++) {
        int e = e0 + i;
        if (e >= ne) continue;
        #pragma unroll
        for (int j = 0; j < 3; j++) {
            float2 s = upk(acc2[i][j]);
            out[(size_t)(base + e) * OUT + o0 + j] = s.x + s.y + b2[o0 + j];
        }
    }
}

// ---------------- host ----------------
extern "C" void kernel_launch(void* const* d_in, const int* in_sizes, int n_in,
                              void* d_out, int out_size)
{
    const float* x      = (const float*)d_in[0];
    const int*   eidx   = (const int*)  d_in[1];
    const float* ea     = (const float*)d_in[2];
    const float* lin1_w = (const float*)d_in[3];
    const float* lin1_b = (const float*)d_in[4];
    const float* cls_w1 = (const float*)d_in[23];
    const float* cls_b1 = (const float*)d_in[24];
    const float* cls_w2 = (const float*)d_in[25];
    const float* cls_b2 = (const float*)d_in[26];

    const int NN = in_sizes[0] / 64;
    const int E  = in_sizes[2] / 32;
    const int* src = eidx;
    const int* dst = eidx + E;

    float *h, *agg, *hid;
    cudaGetSymbolAddress((void**)&h,   g_h);
    cudaGetSymbolAddress((void**)&agg, g_agg);
    cudaGetSymbolAddress((void**)&hid, g_hid);

    const dim3 gnode(1, (unsigned)((NN + BM - 1) / BM));
    const int sblocks = (E + 31) / 32;
    const int cblocks = (E + CLS_E - 1) / CLS_E;
    const int z_n4 = (NN * HID) / 4;
    const int z_blocks = (z_n4 + 255) / 256;

    sgemm_kernel<false><<<gnode, 256>>>(x, nullptr, 64, lin1_w, HID, lin1_b,
                                        h, HID, NN, 64);

    for (int c = 0; c < 3; c++) {
        const float* ew = (const float*)d_in[5 + 6 * c];
        const float* eb = (const float*)d_in[6 + 6 * c];
        const float* w1 = (const float*)d_in[7 + 6 * c];
        const float* b1 = (const float*)d_in[8 + 6 * c];
        const float* w2 = (const float*)d_in[9 + 6 * c];
        const float* b2 = (const float*)d_in[10 + 6 * c];

        zero_kernel<<<z_blocks, 256>>>((float4*)agg, z_n4);
        edge_scatter_kernel<<<sblocks, 128>>>(h, src, dst, ea, ew, eb, agg, E);
        // z = agg + h folded into A-load
        sgemm_kernel<true><<<gnode, 256>>>(agg, h, HID, w1, HID, b1, hid, HID, NN, HID);
        sgemm_kernel<true><<<gnode, 256>>>(hid, nullptr, HID, w2, HID, b2, h, HID, NN, HID);
    }

    sgemm_kernel<false><<<gnode, 256>>>(h, nullptr, HID, cls_w1, HID, nullptr,
                                        hid, HID, NN, HID);
    sgemm_kernel<false><<<gnode, 256>>>(h, nullptr, HID, cls_w1 + 128 * HID, HID, nullptr,
                                        agg, HID, NN, HID);

    cls_fused_kernel<<<cblocks, 128>>>(hid, agg, src, dst, ea,
                                       cls_w1 + 256 * HID, cls_b1,
                                       cls_w2, cls_b2, (float*)d_out, E);
}